// round 11
// baseline (speedup 1.0000x reference)
#include <cuda_runtime.h>

#define NNODES 10000
#define NEDGES 160000
#define CINCH  32
#define H      64
#define T      12
#define OUTC   12
#define KW     3
#define FEAT   (H * T)  // 768

typedef unsigned long long ull;

// ---------------- device scratch (no allocations allowed) ----------------
__device__ float g_bufA[NNODES * FEAT];
__device__ float g_bufB[NNODES * FEAT];
__device__ float g_bufC[NNODES * FEAT];
__device__ float g_dis[NNODES];               // deg accumulator, then rsqrt(deg)
// tconv weights: [c][o(128)][k pad to 4]; one extra channel row for prefetch overrun
__device__ float g_wt1a[(CINCH + 1) * 512];
__device__ float g_wt1b[(H + 1) * 512];
__device__ float g_wt2a[(H + 1) * 512];
__device__ float g_wt2b[(H + 1) * 512];
__device__ ull   g_gc1T[H * H + H];           // dup-packed {w,w}, [c*64 + o], +pad row
__device__ ull   g_gc2T[H * H + H];
// CSR
__device__ int   g_cnt[NNODES];
__device__ int   g_fill[NNODES];
__device__ int   g_row[NNODES + 1];
__device__ ull   g_edge[NEDGES];              // packed {nrm_bits:32, col:32}

// ---------------- f32x2 helpers ----------------
#define FMA2(a, x, y) asm("fma.rn.f32x2 %0, %1, %2, %0;" : "+l"(a) : "l"(x), "l"(y))
__device__ __forceinline__ float lof(ull v) { return __uint_as_float((unsigned)(v & 0xffffffffull)); }
__device__ __forceinline__ float hif(ull v) { return __uint_as_float((unsigned)(v >> 32)); }
__device__ __forceinline__ ull dupr(float f) {
    ull r;
    asm("mov.b64 %0, {%1, %1};" : "=l"(r) : "f"(f));
    return r;
}
__device__ __forceinline__ ull dup2h(float f) {
    unsigned u = __float_as_uint(f);
    return ((ull)u << 32) | (ull)u;
}

// ---------------- fused prep: weight transposes + gcn transposes + deg init ----------
__device__ __forceinline__ void tw_one(const float* __restrict__ w, float* __restrict__ wT,
                                       int cin, int idx) {
    int o = idx / (cin * KW);
    int r = idx - o * cin * KW;
    int c = r / KW;
    int k = r - c * KW;
    wT[(c * 128 + o) * 4 + k] = w[idx];
}

__global__ void k_prep(const float* __restrict__ w1a, const float* __restrict__ w1b,
                       const float* __restrict__ w2a, const float* __restrict__ w2b,
                       const float* __restrict__ gc1, const float* __restrict__ gc2) {
    int idx = blockIdx.x * blockDim.x + threadIdx.x;
    if (idx < 12288) { tw_one(w1a, g_wt1a, CINCH, idx); return; }
    idx -= 12288;
    if (idx < 24576) { tw_one(w1b, g_wt1b, H, idx); return; }
    idx -= 24576;
    if (idx < 24576) { tw_one(w2a, g_wt2a, H, idx); return; }
    idx -= 24576;
    if (idx < 24576) { tw_one(w2b, g_wt2b, H, idx); return; }
    idx -= 24576;
    if (idx < 4096) { int o = idx / H, c = idx - o * H; g_gc1T[c * H + o] = dup2h(gc1[idx]); return; }
    idx -= 4096;
    if (idx < 4096) { int o = idx / H, c = idx - o * H; g_gc2T[c * H + o] = dup2h(gc2[idx]); return; }
    idx -= 4096;
    if (idx < NNODES) { g_dis[idx] = 1.0f; g_cnt[idx] = 0; }
}

__global__ void k_deg_acc(const int* __restrict__ dst, const float* __restrict__ ew) {
    int e = blockIdx.x * blockDim.x + threadIdx.x;
    if (e < NEDGES) {
        int d = dst[e];
        atomicAdd(&g_dis[d], ew[e]);
        atomicAdd(&g_cnt[d], 1);
    }
}

// rsqrt + single-block exclusive scan (warp-shuffle based)
__global__ void k_scan() {
    __shared__ int wsum[32];
    __shared__ int carry_s;
    int tid = threadIdx.x, lane = tid & 31, wid = tid >> 5;
    for (int i = tid; i < NNODES; i += 1024) g_dis[i] = rsqrtf(g_dis[i]);
    if (tid == 0) carry_s = 0;
    __syncthreads();
    for (int base = 0; base < NNODES; base += 1024) {
        int i = base + tid;
        int v = (i < NNODES) ? g_cnt[i] : 0;
        int s = v;
#pragma unroll
        for (int off = 1; off < 32; off <<= 1) {
            int t = __shfl_up_sync(0xffffffffu, s, off);
            if (lane >= off) s += t;
        }
        if (lane == 31) wsum[wid] = s;
        __syncthreads();
        if (wid == 0) {
            int ws = wsum[lane];
#pragma unroll
            for (int off = 1; off < 32; off <<= 1) {
                int t = __shfl_up_sync(0xffffffffu, ws, off);
                if (lane >= off) ws += t;
            }
            wsum[lane] = ws;
        }
        __syncthreads();
        if (i < NNODES) { g_row[i] = carry_s + (wid ? wsum[wid - 1] : 0) + s - v; g_fill[i] = 0; }
        __syncthreads();
        if (tid == 1023) carry_s += wsum[31];
        __syncthreads();
    }
    if (tid == 0) g_row[NNODES] = carry_s;
}

__global__ void k_fill(const int* __restrict__ src, const int* __restrict__ dst,
                       const float* __restrict__ ew) {
    int e = blockIdx.x * blockDim.x + threadIdx.x;
    if (e >= NEDGES) return;
    int s = src[e], d = dst[e];
    int pos = g_row[d] + atomicAdd(&g_fill[d], 1);
    float nrm = g_dis[s] * ew[e] * g_dis[d];
    g_edge[pos] = ((ull)__float_as_uint(nrm) << 32) | (unsigned)s;
}

// ---------------- tconv core, 2 nodes per thread, weight prefetch ----------------
// block: 128 threads = 64 o-channels x 2 node-pairs -> 4 nodes/block.
// xs row per (n,c): 36 floats: xp[0..15] = [0, x0..x11, 0,0,0]; xq[16..27] = [x0..x11]; pad.
template <int CI>
__device__ __forceinline__ void tconv2_core(const float* __restrict__ x,
                                            const float* __restrict__ wT,
                                            const float* __restrict__ b,
                                            float* xs, int tid, int g, int o, int n0,
                                            float (&rA)[12], float (&rB)[12]) {
    for (int idx = tid; idx < 4 * CI * 12; idx += 128) {
        int nn = idx / (CI * 12);
        int rr = idx - nn * (CI * 12);
        int c = rr / 12;
        int t = rr - c * 12;
        float v = x[(n0 + nn) * (CI * 12) + rr];
        float* row = xs + (nn * CI + c) * 36;
        row[t + 1] = v;
        row[16 + t] = v;
    }
    for (int idx = tid; idx < 4 * CI; idx += 128) {
        float* row = xs + idx * 36;
        row[0] = 0.f; row[13] = 0.f; row[14] = 0.f; row[15] = 0.f;
        row[28] = 0.f; row[29] = 0.f; row[30] = 0.f; row[31] = 0.f;
    }
    __syncthreads();

    ull PA[6], QA[6], PB[6], QB[6];
#pragma unroll
    for (int i = 0; i < 6; i++) { PA[i] = 0ull; QA[i] = 0ull; PB[i] = 0ull; QB[i] = 0ull; }

    const ulonglong2* epA = reinterpret_cast<const ulonglong2*>(xs) + (2 * g) * CI * 9;
    const ulonglong2* epB = epA + CI * 9;
    const float4* wv = reinterpret_cast<const float4*>(wT) + o;
    float4 wp4 = wv[0];   // preload c = 0
    float4 wq4 = wv[64];

#pragma unroll 2
    for (int c = 0; c < CI; c++) {
        wv += 128;
        float4 wp4n = wv[0];   // prefetch c+1 (pad row makes last read safe)
        float4 wq4n = wv[64];
        ull w0 = dupr(wp4.x), w1 = dupr(wp4.y), w2 = dupr(wp4.z);
        ull v0 = dupr(wq4.x), v1 = dupr(wq4.y), v2 = dupr(wq4.z);
        {
            ulonglong2 a0 = epA[0], a1 = epA[1], a2 = epA[2], a3 = epA[3];
            ulonglong2 b0 = epA[4], b1 = epA[5], b2 = epA[6];
            epA += 9;
            ull E[8] = {a0.x, a0.y, a1.x, a1.y, a2.x, a2.y, a3.x, a3.y};
            ull O[6] = {b0.x, b0.y, b1.x, b1.y, b2.x, b2.y};
#pragma unroll
            for (int i = 0; i < 6; i++) {
                FMA2(PA[i], w0, E[i]);
                FMA2(PA[i], w1, O[i]);
                FMA2(PA[i], w2, E[i + 1]);
                FMA2(QA[i], v0, E[i]);
                FMA2(QA[i], v1, O[i]);
                FMA2(QA[i], v2, E[i + 1]);
            }
        }
        {
            ulonglong2 a0 = epB[0], a1 = epB[1], a2 = epB[2], a3 = epB[3];
            ulonglong2 b0 = epB[4], b1 = epB[5], b2 = epB[6];
            epB += 9;
            ull E[8] = {a0.x, a0.y, a1.x, a1.y, a2.x, a2.y, a3.x, a3.y};
            ull O[6] = {b0.x, b0.y, b1.x, b1.y, b2.x, b2.y};
#pragma unroll
            for (int i = 0; i < 6; i++) {
                FMA2(PB[i], w0, E[i]);
                FMA2(PB[i], w1, O[i]);
                FMA2(PB[i], w2, E[i + 1]);
                FMA2(QB[i], v0, E[i]);
                FMA2(QB[i], v1, O[i]);
                FMA2(QB[i], v2, E[i + 1]);
            }
        }
        wp4 = wp4n;
        wq4 = wq4n;
    }

    float bp = b[o], bq = b[64 + o];
#pragma unroll
    for (int i = 0; i < 6; i++) {
        float p0 = lof(PA[i]) + bp, p1 = hif(PA[i]) + bp;
        float q0 = lof(QA[i]) + bq, q1 = hif(QA[i]) + bq;
        rA[2 * i]     = p0 * (1.0f / (1.0f + __expf(-q0)));
        rA[2 * i + 1] = p1 * (1.0f / (1.0f + __expf(-q1)));
        p0 = lof(PB[i]) + bp; p1 = hif(PB[i]) + bp;
        q0 = lof(QB[i]) + bq; q1 = hif(QB[i]) + bq;
        rB[2 * i]     = p0 * (1.0f / (1.0f + __expf(-q0)));
        rB[2 * i + 1] = p1 * (1.0f / (1.0f + __expf(-q1)));
    }
}

__device__ __forceinline__ void write12(float* __restrict__ out, int n, int o,
                                        const float (&m)[12]) {
    float4* op = reinterpret_cast<float4*>(out + ((size_t)n * 64 + o) * 12);
    op[0] = make_float4(m[0], m[1], m[2], m[3]);
    op[1] = make_float4(m[4], m[5], m[6], m[7]);
    op[2] = make_float4(m[8], m[9], m[10], m[11]);
}

__device__ __forceinline__ void sb_stage(float* sb, int node_l, int o, const float (&m)[12]) {
    float4* q = reinterpret_cast<float4*>(sb + (node_l * 64 + o) * 20);
    q[0] = make_float4(m[0], m[1], m[2], m[3]);
    q[1] = make_float4(m[4], m[5], m[6], m[7]);
    q[2] = make_float4(m[8], m[9], m[10], m[11]);
}

// ---------------- plain tconv (tconv1b) ----------------
template <int CI>
__global__ void __launch_bounds__(128, 5)
k_tconv2(const float* __restrict__ x, const float* __restrict__ wT,
         const float* __restrict__ b, float* __restrict__ out) {
    __shared__ __align__(16) float xs[4 * CI * 36];
    const int tid = threadIdx.x;
    const int g = tid >> 6;
    const int o = tid & 63;
    const int n0 = blockIdx.x * 4;
    float rA[12], rB[12];
    tconv2_core<CI>(x, wT, b, xs, tid, g, o, n0, rA, rB);
    write12(out, n0 + 2 * g, o, rA);
    write12(out, n0 + 2 * g + 1, o, rB);
}

// ---------------- tconv + channel mix fused ----------------
template <int CI>
__global__ void __launch_bounds__(128, 5)
k_tconv2_mix(const float* __restrict__ x, const float* __restrict__ wT,
             const float* __restrict__ b, const ull* __restrict__ gw,
             float* __restrict__ out) {
    constexpr int XS = 4 * CI * 36;
    constexpr int SB = 4 * 64 * 20;  // 5120
    __shared__ __align__(16) float sm[XS > SB ? XS : SB];
    const int tid = threadIdx.x;
    const int g = tid >> 6;
    const int o = tid & 63;
    const int n0 = blockIdx.x * 4;
    float rA[12], rB[12];
    tconv2_core<CI>(x, wT, b, sm, tid, g, o, n0, rA, rB);

    __syncthreads();  // conv reads of sm done; reuse as sb
    sb_stage(sm, 2 * g, o, rA);
    sb_stage(sm, 2 * g + 1, o, rB);
    __syncthreads();

    ull MA[6], MB[6];
#pragma unroll
    for (int i = 0; i < 6; i++) { MA[i] = 0ull; MB[i] = 0ull; }
    const ulonglong2* spA = reinterpret_cast<const ulonglong2*>(sm) + (2 * g) * 64 * 5;
    const ulonglong2* spB = spA + 64 * 5;
    const ull* gp = gw + o;
    ull w = gp[0];  // preload c = 0
#pragma unroll 2
    for (int c = 0; c < 64; c++) {
        gp += 64;
        ull wn = gp[0];  // prefetch (pad row covers last iter)
        ulonglong2 a0 = spA[0], a1 = spA[1], a2 = spA[2];
        spA += 5;
        FMA2(MA[0], w, a0.x); FMA2(MA[1], w, a0.y);
        FMA2(MA[2], w, a1.x); FMA2(MA[3], w, a1.y);
        FMA2(MA[4], w, a2.x); FMA2(MA[5], w, a2.y);
        ulonglong2 c0 = spB[0], c1 = spB[1], c2 = spB[2];
        spB += 5;
        FMA2(MB[0], w, c0.x); FMA2(MB[1], w, c0.y);
        FMA2(MB[2], w, c1.x); FMA2(MB[3], w, c1.y);
        FMA2(MB[4], w, c2.x); FMA2(MB[5], w, c2.y);
        w = wn;
    }
    float mA[12], mB[12];
#pragma unroll
    for (int i = 0; i < 6; i++) {
        mA[2 * i] = lof(MA[i]); mA[2 * i + 1] = hif(MA[i]);
        mB[2 * i] = lof(MB[i]); mB[2 * i + 1] = hif(MB[i]);
    }
    write12(out, n0 + 2 * g, o, mA);
    write12(out, n0 + 2 * g + 1, o, mB);
}

// ---------------- tconv + final 1x12 conv fused ----------------
__global__ void __launch_bounds__(128, 5)
k_tconv2_fin(const float* __restrict__ x, const float* __restrict__ wT,
             const float* __restrict__ b, const float* __restrict__ fw,
             const float* __restrict__ fb, float* __restrict__ out) {
    constexpr int XS = 4 * H * 36;   // 9216
    __shared__ __align__(16) float sm[XS];
    const int tid = threadIdx.x;
    const int g = tid >> 6;
    const int o = tid & 63;
    const int n0 = blockIdx.x * 4;
    float rA[12], rB[12];
    tconv2_core<H>(x, wT, b, sm, tid, g, o, n0, rA, rB);

    __syncthreads();
    sb_stage(sm, 2 * g, o, rA);
    sb_stage(sm, 2 * g + 1, o, rB);
    __syncthreads();

    // fin: 96 threads: nl(0..3) x oc(0..11) x half(0..1); dot over 32 c x 12 t; shfl add.
    if (tid < 96) {
        int nl = tid / 24;
        int rr = tid - nl * 24;
        int oc = rr >> 1;
        int s2 = rr & 1;
        const float* gS = sm + nl * 64 * 20 + s2 * 32 * 20;
        const float4* wrow = reinterpret_cast<const float4*>(fw + oc * FEAT + s2 * 32 * 12);
        float acc = 0.0f;
#pragma unroll 4
        for (int c = 0; c < 32; c++) {
            const float4* sr = reinterpret_cast<const float4*>(gS + c * 20);
            float4 a0 = sr[0], a1 = sr[1], a2 = sr[2];
            float4 w0 = wrow[0], w1v = wrow[1], w2 = wrow[2];
            wrow += 3;
            acc += a0.x * w0.x + a0.y * w0.y + a0.z * w0.z + a0.w * w0.w;
            acc += a1.x * w1v.x + a1.y * w1v.y + a1.z * w1v.z + a1.w * w1v.w;
            acc += a2.x * w2.x + a2.y * w2.y + a2.z * w2.z + a2.w * w2.w;
        }
        acc += __shfl_xor_sync(0xffffffffu, acc, 1);
        if (s2 == 0) out[(n0 + nl) * 12 + oc] = acc + fb[oc];
    }
}

// ---------------- GCN gather: out[n] = relu(b + dis[n]^2 * x[n] + sum_e nrm*x[src]) --------
__global__ void __launch_bounds__(192)
k_gather(const float* __restrict__ x, float* __restrict__ out, const float* __restrict__ b) {
    const int n = blockIdx.x;
    const int j = threadIdx.x;  // 0..191 float4 slots
    float bb = b[j / 3];
    float ds = g_dis[n];
    float sc = ds * ds;
    const float4* xv = reinterpret_cast<const float4*>(x);
    float4 v = xv[(size_t)n * 192 + j];
    float4 acc = make_float4(bb + sc * v.x, bb + sc * v.y, bb + sc * v.z, bb + sc * v.w);
    int e = g_row[n];
    const int end = g_row[n + 1];
    for (; e + 1 < end; e += 2) {
        ull e0 = __ldg(&g_edge[e]);
        ull e1 = __ldg(&g_edge[e + 1]);
        int s0 = (int)(unsigned)e0, s1 = (int)(unsigned)e1;
        float c0 = __uint_as_float((unsigned)(e0 >> 32));
        float c1 = __uint_as_float((unsigned)(e1 >> 32));
        float4 u0 = xv[(size_t)s0 * 192 + j];
        float4 u1 = xv[(size_t)s1 * 192 + j];
        acc.x += c0 * u0.x + c1 * u1.x;
        acc.y += c0 * u0.y + c1 * u1.y;
        acc.z += c0 * u0.z + c1 * u1.z;
        acc.w += c0 * u0.w + c1 * u1.w;
    }
    if (e < end) {
        ull e0 = __ldg(&g_edge[e]);
        int s0 = (int)(unsigned)e0;
        float c0 = __uint_as_float((unsigned)(e0 >> 32));
        float4 u0 = xv[(size_t)s0 * 192 + j];
        acc.x += c0 * u0.x; acc.y += c0 * u0.y; acc.z += c0 * u0.z; acc.w += c0 * u0.w;
    }
    reinterpret_cast<float4*>(out)[(size_t)n * 192 + j] =
        make_float4(fmaxf(acc.x, 0.f), fmaxf(acc.y, 0.f), fmaxf(acc.z, 0.f), fmaxf(acc.w, 0.f));
}

// ---------------- launch ----------------
extern "C" void kernel_launch(void* const* d_in, const int* in_sizes, int n_in,
                              void* d_out, int out_size) {
    const float* x      = (const float*)d_in[0];
    const int*   ei     = (const int*)d_in[1];
    const int*   src    = ei;
    const int*   dst    = ei + NEDGES;
    const float* ew     = (const float*)d_in[2];
    const float* tc1a_w = (const float*)d_in[3];
    const float* tc1a_b = (const float*)d_in[4];
    const float* gc1_w  = (const float*)d_in[5];
    const float* gc1_b  = (const float*)d_in[6];
    const float* tc1b_w = (const float*)d_in[7];
    const float* tc1b_b = (const float*)d_in[8];
    const float* tc2a_w = (const float*)d_in[9];
    const float* tc2a_b = (const float*)d_in[10];
    const float* gc2_w  = (const float*)d_in[11];
    const float* gc2_b  = (const float*)d_in[12];
    const float* tc2b_w = (const float*)d_in[13];
    const float* tc2b_b = (const float*)d_in[14];
    const float* fin_w  = (const float*)d_in[15];
    const float* fin_b  = (const float*)d_in[16];
    float* out = (float*)d_out;

    float *bA, *bB, *bC, *w1a, *w1b, *w2a, *w2b;
    ull *g1, *g2;
    cudaGetSymbolAddress((void**)&bA, g_bufA);
    cudaGetSymbolAddress((void**)&bB, g_bufB);
    cudaGetSymbolAddress((void**)&bC, g_bufC);
    cudaGetSymbolAddress((void**)&w1a, g_wt1a);
    cudaGetSymbolAddress((void**)&w1b, g_wt1b);
    cudaGetSymbolAddress((void**)&w2a, g_wt2a);
    cudaGetSymbolAddress((void**)&w2b, g_wt2b);
    cudaGetSymbolAddress((void**)&g1, g_gc1T);
    cudaGetSymbolAddress((void**)&g2, g_gc2T);

    const int NB = NNODES / 4;  // 2500

    // launches 1..3: prep (tconv1a+mix has no CSR dependency; CSR build happens later)
    const int PREP_TOT = 12288 + 3 * 24576 + 2 * 4096 + NNODES;
    k_prep<<<(PREP_TOT + 255) / 256, 256>>>(tc1a_w, tc1b_w, tc2a_w, tc2b_w, gc1_w, gc2_w);
    k_deg_acc<<<(NEDGES + 255) / 256, 256>>>(dst, ew);
    k_scan<<<1, 1024>>>();

    // launch 4: hot kernel at the ncu capture position
    k_tconv2_mix<CINCH><<<NB, 128>>>(x, w1a, tc1a_b, g1, bA);   // tconv1a + mix1

    // CSR fill, then the rest of the pipeline
    k_fill<<<(NEDGES + 255) / 256, 256>>>(src, dst, ew);
    k_gather<<<NNODES, 192>>>(bA, bB, gc1_b);                    // +bias +selfloop +relu
    k_tconv2<H><<<NB, 128>>>(bB, w1b, tc1b_b, bC);               // tconv1b
    k_tconv2_mix<H><<<NB, 128>>>(bC, w2a, tc2a_b, g2, bA);       // tconv2a + mix2
    k_gather<<<NNODES, 192>>>(bA, bB, gc2_b);
    k_tconv2_fin<<<NB, 128>>>(bB, w2b, tc2b_b, fin_w, fin_b, out);  // tconv2b + fin
}

// round 12
// speedup vs baseline: 1.0486x; 1.0486x over previous
#include <cuda_runtime.h>

#define NNODES 10000
#define NEDGES 160000
#define CINCH  32
#define H      64
#define T      12
#define OUTC   12
#define KW     3
#define FEAT   (H * T)  // 768

typedef unsigned long long ull;

// ---------------- device scratch (no allocations allowed) ----------------
__device__ float g_bufA[NNODES * FEAT];
__device__ float g_bufB[NNODES * FEAT];
__device__ float g_bufC[NNODES * FEAT];
__device__ float g_dis[NNODES];               // deg accumulator, then rsqrt(deg)
// tconv weights: [c][o(128)][k pad to 4]; one extra channel row for prefetch overrun
__device__ float g_wt1a[(CINCH + 1) * 512];
__device__ float g_wt1b[(H + 1) * 512];
__device__ float g_wt2a[(H + 1) * 512];
__device__ float g_wt2b[(H + 1) * 512];
__device__ ull   g_gc1T[H * H + H];           // dup-packed {w,w}, [c*64 + o], +pad row
__device__ ull   g_gc2T[H * H + H];
// CSR
__device__ int   g_cnt[NNODES];
__device__ int   g_fill[NNODES];
__device__ int   g_row[NNODES + 1];
__device__ ull   g_edge[NEDGES];              // packed {nrm_bits:32, col:32}

// ---------------- f32x2 helpers ----------------
#define FMA2(a, x, y) asm("fma.rn.f32x2 %0, %1, %2, %0;" : "+l"(a) : "l"(x), "l"(y))
__device__ __forceinline__ float lof(ull v) { return __uint_as_float((unsigned)(v & 0xffffffffull)); }
__device__ __forceinline__ float hif(ull v) { return __uint_as_float((unsigned)(v >> 32)); }
__device__ __forceinline__ ull dupr(float f) {
    ull r;
    asm("mov.b64 %0, {%1, %1};" : "=l"(r) : "f"(f));
    return r;
}
__device__ __forceinline__ ull packf2(float lo, float hi) {
    ull r;
    asm("mov.b64 %0, {%1, %2};" : "=l"(r) : "f"(lo), "f"(hi));
    return r;
}
__device__ __forceinline__ ull dup2h(float f) {
    unsigned u = __float_as_uint(f);
    return ((ull)u << 32) | (ull)u;
}

// ---------------- fused prep: weight transposes + gcn transposes + deg init ----------
__device__ __forceinline__ void tw_one(const float* __restrict__ w, float* __restrict__ wT,
                                       int cin, int idx) {
    int o = idx / (cin * KW);
    int r = idx - o * cin * KW;
    int c = r / KW;
    int k = r - c * KW;
    wT[(c * 128 + o) * 4 + k] = w[idx];
}

__global__ void k_prep(const float* __restrict__ w1a, const float* __restrict__ w1b,
                       const float* __restrict__ w2a, const float* __restrict__ w2b,
                       const float* __restrict__ gc1, const float* __restrict__ gc2) {
    int idx = blockIdx.x * blockDim.x + threadIdx.x;
    if (idx < 12288) { tw_one(w1a, g_wt1a, CINCH, idx); return; }
    idx -= 12288;
    if (idx < 24576) { tw_one(w1b, g_wt1b, H, idx); return; }
    idx -= 24576;
    if (idx < 24576) { tw_one(w2a, g_wt2a, H, idx); return; }
    idx -= 24576;
    if (idx < 24576) { tw_one(w2b, g_wt2b, H, idx); return; }
    idx -= 24576;
    if (idx < 4096) { int o = idx / H, c = idx - o * H; g_gc1T[c * H + o] = dup2h(gc1[idx]); return; }
    idx -= 4096;
    if (idx < 4096) { int o = idx / H, c = idx - o * H; g_gc2T[c * H + o] = dup2h(gc2[idx]); return; }
    idx -= 4096;
    if (idx < NNODES) { g_dis[idx] = 1.0f; g_cnt[idx] = 0; }
}

__global__ void k_deg_acc(const int* __restrict__ dst, const float* __restrict__ ew) {
    int e = blockIdx.x * blockDim.x + threadIdx.x;
    if (e < NEDGES) {
        int d = dst[e];
        atomicAdd(&g_dis[d], ew[e]);
        atomicAdd(&g_cnt[d], 1);
    }
}

// rsqrt + single-block exclusive scan (warp-shuffle based)
__global__ void k_scan() {
    __shared__ int wsum[32];
    __shared__ int carry_s;
    int tid = threadIdx.x, lane = tid & 31, wid = tid >> 5;
    for (int i = tid; i < NNODES; i += 1024) g_dis[i] = rsqrtf(g_dis[i]);
    if (tid == 0) carry_s = 0;
    __syncthreads();
    for (int base = 0; base < NNODES; base += 1024) {
        int i = base + tid;
        int v = (i < NNODES) ? g_cnt[i] : 0;
        int s = v;
#pragma unroll
        for (int off = 1; off < 32; off <<= 1) {
            int t = __shfl_up_sync(0xffffffffu, s, off);
            if (lane >= off) s += t;
        }
        if (lane == 31) wsum[wid] = s;
        __syncthreads();
        if (wid == 0) {
            int ws = wsum[lane];
#pragma unroll
            for (int off = 1; off < 32; off <<= 1) {
                int t = __shfl_up_sync(0xffffffffu, ws, off);
                if (lane >= off) ws += t;
            }
            wsum[lane] = ws;
        }
        __syncthreads();
        if (i < NNODES) { g_row[i] = carry_s + (wid ? wsum[wid - 1] : 0) + s - v; g_fill[i] = 0; }
        __syncthreads();
        if (tid == 1023) carry_s += wsum[31];
        __syncthreads();
    }
    if (tid == 0) g_row[NNODES] = carry_s;
}

__global__ void k_fill(const int* __restrict__ src, const int* __restrict__ dst,
                       const float* __restrict__ ew) {
    int e = blockIdx.x * blockDim.x + threadIdx.x;
    if (e >= NEDGES) return;
    int s = src[e], d = dst[e];
    int pos = g_row[d] + atomicAdd(&g_fill[d], 1);
    float nrm = g_dis[s] * ew[e] * g_dis[d];
    g_edge[pos] = ((ull)__float_as_uint(nrm) << 32) | (unsigned)s;
}

// ---------------- tconv core, pair-window layout {t, t+6} ----------------
// block: 128 threads = 64 o-channels x 2 node-pairs -> 4 nodes/block.
// xs row per (n,c): 10 ull, W[m] = {x[m-1], x[m+5]} for m=0..7 (x[-1]=x[12]=0), 2 pad.
// Tap math: out pair P_i = {t=i, t=i+6};  P_i += w_k * W[i+k],  i=0..5, k=0..2.
template <int CI>
__device__ __forceinline__ void tconv2_core(const float* __restrict__ x,
                                            const float* __restrict__ wT,
                                            const float* __restrict__ b,
                                            ull* xs, int tid, int g, int o, int n0,
                                            float (&rAlo)[6], float (&rAhi)[6],
                                            float (&rBlo)[6], float (&rBhi)[6]) {
    for (int idx = tid; idx < 4 * CI * 12; idx += 128) {
        int nn = idx / (CI * 12);
        int rr = idx - nn * (CI * 12);
        int c = rr / 12;
        int t = rr - c * 12;
        float v = x[(n0 + nn) * (CI * 12) + rr];
        float* row = (float*)(xs + (nn * CI + c) * 10);
        if (t <= 6) row[2 * (t + 1)] = v;      // W[t+1].lo = x[t]
        if (t >= 5) row[2 * (t - 5) + 1] = v;  // W[t-5].hi = x[t]
    }
    for (int idx = tid; idx < 4 * CI; idx += 128) {
        float* row = (float*)(xs + idx * 10);
        row[0] = 0.f;   // W[0].lo = x[-1]
        row[15] = 0.f;  // W[7].hi = x[12]
    }
    __syncthreads();

    ull PA[6], QA[6], PB[6], QB[6];
#pragma unroll
    for (int i = 0; i < 6; i++) { PA[i] = 0ull; QA[i] = 0ull; PB[i] = 0ull; QB[i] = 0ull; }

    const ulonglong2* epA = reinterpret_cast<const ulonglong2*>(xs + (2 * g) * CI * 10);
    const ulonglong2* epB = reinterpret_cast<const ulonglong2*>(xs + (2 * g + 1) * CI * 10);
    const float4* wv = reinterpret_cast<const float4*>(wT) + o;
    float4 wp4 = wv[0];   // preload c = 0
    float4 wq4 = wv[64];

#pragma unroll 2
    for (int c = 0; c < CI; c++) {
        wv += 128;
        float4 wp4n = wv[0];   // prefetch c+1 (pad row makes last read safe)
        float4 wq4n = wv[64];
        ull w0 = dupr(wp4.x), w1 = dupr(wp4.y), w2 = dupr(wp4.z);
        ull v0 = dupr(wq4.x), v1 = dupr(wq4.y), v2 = dupr(wq4.z);
        {
            ulonglong2 a0 = epA[0], a1 = epA[1], a2 = epA[2], a3 = epA[3];
            epA += 5;
            ull W[8] = {a0.x, a0.y, a1.x, a1.y, a2.x, a2.y, a3.x, a3.y};
#pragma unroll
            for (int i = 0; i < 6; i++) {
                FMA2(PA[i], w0, W[i]);
                FMA2(PA[i], w1, W[i + 1]);
                FMA2(PA[i], w2, W[i + 2]);
                FMA2(QA[i], v0, W[i]);
                FMA2(QA[i], v1, W[i + 1]);
                FMA2(QA[i], v2, W[i + 2]);
            }
        }
        {
            ulonglong2 a0 = epB[0], a1 = epB[1], a2 = epB[2], a3 = epB[3];
            epB += 5;
            ull W[8] = {a0.x, a0.y, a1.x, a1.y, a2.x, a2.y, a3.x, a3.y};
#pragma unroll
            for (int i = 0; i < 6; i++) {
                FMA2(PB[i], w0, W[i]);
                FMA2(PB[i], w1, W[i + 1]);
                FMA2(PB[i], w2, W[i + 2]);
                FMA2(QB[i], v0, W[i]);
                FMA2(QB[i], v1, W[i + 1]);
                FMA2(QB[i], v2, W[i + 2]);
            }
        }
        wp4 = wp4n;
        wq4 = wq4n;
    }

    float bp = b[o], bq = b[64 + o];
#pragma unroll
    for (int i = 0; i < 6; i++) {
        float pl = lof(PA[i]) + bp, ph = hif(PA[i]) + bp;
        float ql = lof(QA[i]) + bq, qh = hif(QA[i]) + bq;
        rAlo[i] = pl * (1.0f / (1.0f + __expf(-ql)));
        rAhi[i] = ph * (1.0f / (1.0f + __expf(-qh)));
        pl = lof(PB[i]) + bp; ph = hif(PB[i]) + bp;
        ql = lof(QB[i]) + bq; qh = hif(QB[i]) + bq;
        rBlo[i] = pl * (1.0f / (1.0f + __expf(-ql)));
        rBhi[i] = ph * (1.0f / (1.0f + __expf(-qh)));
    }
}

// write pairs {i, i+6} out in t-order
__device__ __forceinline__ void write12p(float* __restrict__ out, int n, int o,
                                         const float (&lo6)[6], const float (&hi6)[6]) {
    float4* op = reinterpret_cast<float4*>(out + ((size_t)n * 64 + o) * 12);
    op[0] = make_float4(lo6[0], lo6[1], lo6[2], lo6[3]);
    op[1] = make_float4(lo6[4], lo6[5], hi6[0], hi6[1]);
    op[2] = make_float4(hi6[2], hi6[3], hi6[4], hi6[5]);
}

// stage pairs into sb (10-ull row per (node, o))
__device__ __forceinline__ void sb_stage_p(ull* sb, int node_l, int o,
                                           const float (&lo6)[6], const float (&hi6)[6]) {
    ull* q = sb + (node_l * 64 + o) * 10;
#pragma unroll
    for (int i = 0; i < 6; i++) q[i] = packf2(lo6[i], hi6[i]);
}

// ---------------- plain tconv (tconv1b) ----------------
template <int CI>
__global__ void __launch_bounds__(128, 5)
k_tconv2(const float* __restrict__ x, const float* __restrict__ wT,
         const float* __restrict__ b, float* __restrict__ out) {
    __shared__ __align__(16) ull xs[4 * CI * 10];
    const int tid = threadIdx.x;
    const int g = tid >> 6;
    const int o = tid & 63;
    const int n0 = blockIdx.x * 4;
    float rAlo[6], rAhi[6], rBlo[6], rBhi[6];
    tconv2_core<CI>(x, wT, b, xs, tid, g, o, n0, rAlo, rAhi, rBlo, rBhi);
    write12p(out, n0 + 2 * g, o, rAlo, rAhi);
    write12p(out, n0 + 2 * g + 1, o, rBlo, rBhi);
}

// ---------------- tconv + channel mix fused ----------------
template <int CI>
__global__ void __launch_bounds__(128, 5)
k_tconv2_mix(const float* __restrict__ x, const float* __restrict__ wT,
             const float* __restrict__ b, const ull* __restrict__ gw,
             float* __restrict__ out) {
    constexpr int XS = 4 * CI * 10;
    constexpr int SB = 4 * 64 * 10;  // 2560 ull = 20 KB
    __shared__ __align__(16) ull sm[XS > SB ? XS : SB];
    const int tid = threadIdx.x;
    const int g = tid >> 6;
    const int o = tid & 63;
    const int n0 = blockIdx.x * 4;
    float rAlo[6], rAhi[6], rBlo[6], rBhi[6];
    tconv2_core<CI>(x, wT, b, sm, tid, g, o, n0, rAlo, rAhi, rBlo, rBhi);

    __syncthreads();  // conv reads of sm done; reuse as sb
    sb_stage_p(sm, 2 * g, o, rAlo, rAhi);
    sb_stage_p(sm, 2 * g + 1, o, rBlo, rBhi);
    __syncthreads();

    ull MA[6], MB[6];
#pragma unroll
    for (int i = 0; i < 6; i++) { MA[i] = 0ull; MB[i] = 0ull; }
    const ulonglong2* spA = reinterpret_cast<const ulonglong2*>(sm + (2 * g) * 64 * 10);
    const ulonglong2* spB = reinterpret_cast<const ulonglong2*>(sm + (2 * g + 1) * 64 * 10);
    const ull* gp = gw + o;
    ull w = gp[0];  // preload c = 0
#pragma unroll 2
    for (int c = 0; c < 64; c++) {
        gp += 64;
        ull wn = gp[0];  // prefetch (pad row covers last iter)
        ulonglong2 a0 = spA[0], a1 = spA[1], a2 = spA[2];
        spA += 5;
        FMA2(MA[0], w, a0.x); FMA2(MA[1], w, a0.y);
        FMA2(MA[2], w, a1.x); FMA2(MA[3], w, a1.y);
        FMA2(MA[4], w, a2.x); FMA2(MA[5], w, a2.y);
        ulonglong2 c0 = spB[0], c1 = spB[1], c2 = spB[2];
        spB += 5;
        FMA2(MB[0], w, c0.x); FMA2(MB[1], w, c0.y);
        FMA2(MB[2], w, c1.x); FMA2(MB[3], w, c1.y);
        FMA2(MB[4], w, c2.x); FMA2(MB[5], w, c2.y);
        w = wn;
    }
    float mAlo[6], mAhi[6], mBlo[6], mBhi[6];
#pragma unroll
    for (int i = 0; i < 6; i++) {
        mAlo[i] = lof(MA[i]); mAhi[i] = hif(MA[i]);
        mBlo[i] = lof(MB[i]); mBhi[i] = hif(MB[i]);
    }
    write12p(out, n0 + 2 * g, o, mAlo, mAhi);
    write12p(out, n0 + 2 * g + 1, o, mBlo, mBhi);
}

// ---------------- tconv + final 1x12 conv fused ----------------
__global__ void __launch_bounds__(128, 5)
k_tconv2_fin(const float* __restrict__ x, const float* __restrict__ wT,
             const float* __restrict__ b, const float* __restrict__ fw,
             const float* __restrict__ fb, float* __restrict__ out) {
    constexpr int XS = 4 * H * 10;  // 2560 = same as SB
    __shared__ __align__(16) ull sm[XS];
    const int tid = threadIdx.x;
    const int g = tid >> 6;
    const int o = tid & 63;
    const int n0 = blockIdx.x * 4;
    float rAlo[6], rAhi[6], rBlo[6], rBhi[6];
    tconv2_core<H>(x, wT, b, sm, tid, g, o, n0, rAlo, rAhi, rBlo, rBhi);

    __syncthreads();
    sb_stage_p(sm, 2 * g, o, rAlo, rAhi);
    sb_stage_p(sm, 2 * g + 1, o, rBlo, rBhi);
    __syncthreads();

    // fin: 96 threads: nl(0..3) x oc(0..11) x half(0..1); dot over 32 c x 12 t; shfl add.
    if (tid < 96) {
        int nl = tid / 24;
        int rr = tid - nl * 24;
        int oc = rr >> 1;
        int s2 = rr & 1;
        const ull* gS = sm + (nl * 64 + s2 * 32) * 10;
        const float4* wrow = reinterpret_cast<const float4*>(fw + oc * FEAT + s2 * 32 * 12);
        float acc = 0.0f;
#pragma unroll 4
        for (int c = 0; c < 32; c++) {
            const ulonglong2* sr = reinterpret_cast<const ulonglong2*>(gS + c * 10);
            ulonglong2 a0 = sr[0], a1 = sr[1], a2 = sr[2];
            float4 w0 = wrow[0], w1v = wrow[1], w2 = wrow[2];
            wrow += 3;
            acc += lof(a0.x) * w0.x + lof(a0.y) * w0.y + lof(a1.x) * w0.z + lof(a1.y) * w0.w;
            acc += lof(a2.x) * w1v.x + lof(a2.y) * w1v.y;
            acc += hif(a0.x) * w1v.z + hif(a0.y) * w1v.w;
            acc += hif(a1.x) * w2.x + hif(a1.y) * w2.y + hif(a2.x) * w2.z + hif(a2.y) * w2.w;
        }
        acc += __shfl_xor_sync(0xffffffffu, acc, 1);
        if (s2 == 0) out[(n0 + nl) * 12 + oc] = acc + fb[oc];
    }
}

// ---------------- GCN gather: out[n] = relu(b + dis[n]^2 * x[n] + sum_e nrm*x[src]) --------
__global__ void __launch_bounds__(192)
k_gather(const float* __restrict__ x, float* __restrict__ out, const float* __restrict__ b) {
    const int n = blockIdx.x;
    const int j = threadIdx.x;  // 0..191 float4 slots
    float bb = b[j / 3];
    float ds = g_dis[n];
    float sc = ds * ds;
    const float4* xv = reinterpret_cast<const float4*>(x);
    float4 v = xv[(size_t)n * 192 + j];
    float4 acc = make_float4(bb + sc * v.x, bb + sc * v.y, bb + sc * v.z, bb + sc * v.w);
    int e = g_row[n];
    const int end = g_row[n + 1];
    for (; e + 1 < end; e += 2) {
        ull e0 = __ldg(&g_edge[e]);
        ull e1 = __ldg(&g_edge[e + 1]);
        int s0 = (int)(unsigned)e0, s1 = (int)(unsigned)e1;
        float c0 = __uint_as_float((unsigned)(e0 >> 32));
        float c1 = __uint_as_float((unsigned)(e1 >> 32));
        float4 u0 = xv[(size_t)s0 * 192 + j];
        float4 u1 = xv[(size_t)s1 * 192 + j];
        acc.x += c0 * u0.x + c1 * u1.x;
        acc.y += c0 * u0.y + c1 * u1.y;
        acc.z += c0 * u0.z + c1 * u1.z;
        acc.w += c0 * u0.w + c1 * u1.w;
    }
    if (e < end) {
        ull e0 = __ldg(&g_edge[e]);
        int s0 = (int)(unsigned)e0;
        float c0 = __uint_as_float((unsigned)(e0 >> 32));
        float4 u0 = xv[(size_t)s0 * 192 + j];
        acc.x += c0 * u0.x; acc.y += c0 * u0.y; acc.z += c0 * u0.z; acc.w += c0 * u0.w;
    }
    reinterpret_cast<float4*>(out)[(size_t)n * 192 + j] =
        make_float4(fmaxf(acc.x, 0.f), fmaxf(acc.y, 0.f), fmaxf(acc.z, 0.f), fmaxf(acc.w, 0.f));
}

// ---------------- launch ----------------
extern "C" void kernel_launch(void* const* d_in, const int* in_sizes, int n_in,
                              void* d_out, int out_size) {
    const float* x      = (const float*)d_in[0];
    const int*   ei     = (const int*)d_in[1];
    const int*   src    = ei;
    const int*   dst    = ei + NEDGES;
    const float* ew     = (const float*)d_in[2];
    const float* tc1a_w = (const float*)d_in[3];
    const float* tc1a_b = (const float*)d_in[4];
    const float* gc1_w  = (const float*)d_in[5];
    const float* gc1_b  = (const float*)d_in[6];
    const float* tc1b_w = (const float*)d_in[7];
    const float* tc1b_b = (const float*)d_in[8];
    const float* tc2a_w = (const float*)d_in[9];
    const float* tc2a_b = (const float*)d_in[10];
    const float* gc2_w  = (const float*)d_in[11];
    const float* gc2_b  = (const float*)d_in[12];
    const float* tc2b_w = (const float*)d_in[13];
    const float* tc2b_b = (const float*)d_in[14];
    const float* fin_w  = (const float*)d_in[15];
    const float* fin_b  = (const float*)d_in[16];
    float* out = (float*)d_out;

    float *bA, *bB, *bC, *w1a, *w1b, *w2a, *w2b;
    ull *g1, *g2;
    cudaGetSymbolAddress((void**)&bA, g_bufA);
    cudaGetSymbolAddress((void**)&bB, g_bufB);
    cudaGetSymbolAddress((void**)&bC, g_bufC);
    cudaGetSymbolAddress((void**)&w1a, g_wt1a);
    cudaGetSymbolAddress((void**)&w1b, g_wt1b);
    cudaGetSymbolAddress((void**)&w2a, g_wt2a);
    cudaGetSymbolAddress((void**)&w2b, g_wt2b);
    cudaGetSymbolAddress((void**)&g1, g_gc1T);
    cudaGetSymbolAddress((void**)&g2, g_gc2T);

    const int NB = NNODES / 4;  // 2500

    // launches 1..3: prep (tconv1a+mix has no CSR dependency; CSR build happens later)
    const int PREP_TOT = 12288 + 3 * 24576 + 2 * 4096 + NNODES;
    k_prep<<<(PREP_TOT + 255) / 256, 256>>>(tc1a_w, tc1b_w, tc2a_w, tc2b_w, gc1_w, gc2_w);
    k_deg_acc<<<(NEDGES + 255) / 256, 256>>>(dst, ew);
    k_scan<<<1, 1024>>>();

    // launch 4: hot kernel at the ncu capture position
    k_tconv2_mix<CINCH><<<NB, 128>>>(x, w1a, tc1a_b, g1, bA);   // tconv1a + mix1

    // CSR fill, then the rest of the pipeline
    k_fill<<<(NEDGES + 255) / 256, 256>>>(src, dst, ew);
    k_gather<<<NNODES, 192>>>(bA, bB, gc1_b);                    // +bias +selfloop +relu
    k_tconv2<H><<<NB, 128>>>(bB, w1b, tc1b_b, bC);               // tconv1b
    k_tconv2_mix<H><<<NB, 128>>>(bC, w2a, tc2a_b, g2, bA);       // tconv2a + mix2
    k_gather<<<NNODES, 192>>>(bA, bB, gc2_b);
    k_tconv2_fin<<<NB, 128>>>(bB, w2b, tc2b_b, fin_w, fin_b, out);  // tconv2b + fin
}

// round 13
// speedup vs baseline: 1.0822x; 1.0320x over previous
#include <cuda_runtime.h>

#define NNODES 10000
#define NEDGES 160000
#define CINCH  32
#define H      64
#define T      12
#define OUTC   12
#define KW     3
#define FEAT   (H * T)  // 768

typedef unsigned long long ull;

// ---------------- device scratch (no allocations allowed) ----------------
__device__ float g_bufA[NNODES * FEAT];
__device__ float g_bufB[NNODES * FEAT];
__device__ float g_dis[NNODES];               // deg accumulator, then rsqrt(deg)
// tconv weights: [c][o(128)][k pad to 4]; one extra channel row for prefetch overrun
__device__ float g_wt1a[(CINCH + 1) * 512];
__device__ float g_wt1b[(H + 1) * 512];
__device__ float g_wt2a[(H + 1) * 512];
__device__ float g_wt2b[(H + 1) * 512];
__device__ ull   g_gc1T[H * H + H];           // dup-packed {w,w}, [c*64 + o], +pad row
__device__ ull   g_gc2T[H * H + H];
// CSR
__device__ int   g_cnt[NNODES];
__device__ int   g_fill[NNODES];
__device__ int   g_row[NNODES + 1];
__device__ ull   g_edge[NEDGES];              // packed {nrm_bits:32, col:32}

// ---------------- f32x2 helpers ----------------
#define FMA2(a, x, y) asm("fma.rn.f32x2 %0, %1, %2, %0;" : "+l"(a) : "l"(x), "l"(y))
__device__ __forceinline__ float lof(ull v) { return __uint_as_float((unsigned)(v & 0xffffffffull)); }
__device__ __forceinline__ float hif(ull v) { return __uint_as_float((unsigned)(v >> 32)); }
__device__ __forceinline__ ull dupr(float f) {
    ull r;
    asm("mov.b64 %0, {%1, %1};" : "=l"(r) : "f"(f));
    return r;
}
__device__ __forceinline__ ull packf2(float lo, float hi) {
    ull r;
    asm("mov.b64 %0, {%1, %2};" : "=l"(r) : "f"(lo), "f"(hi));
    return r;
}
__device__ __forceinline__ ull dup2h(float f) {
    unsigned u = __float_as_uint(f);
    return ((ull)u << 32) | (ull)u;
}

// ---------------- fused prep: weight transposes + gcn transposes + deg init ----------
__device__ __forceinline__ void tw_one(const float* __restrict__ w, float* __restrict__ wT,
                                       int cin, int idx) {
    int o = idx / (cin * KW);
    int r = idx - o * cin * KW;
    int c = r / KW;
    int k = r - c * KW;
    wT[(c * 128 + o) * 4 + k] = w[idx];
}

__global__ void k_prep(const float* __restrict__ w1a, const float* __restrict__ w1b,
                       const float* __restrict__ w2a, const float* __restrict__ w2b,
                       const float* __restrict__ gc1, const float* __restrict__ gc2) {
    int idx = blockIdx.x * blockDim.x + threadIdx.x;
    if (idx < 12288) { tw_one(w1a, g_wt1a, CINCH, idx); return; }
    idx -= 12288;
    if (idx < 24576) { tw_one(w1b, g_wt1b, H, idx); return; }
    idx -= 24576;
    if (idx < 24576) { tw_one(w2a, g_wt2a, H, idx); return; }
    idx -= 24576;
    if (idx < 24576) { tw_one(w2b, g_wt2b, H, idx); return; }
    idx -= 24576;
    if (idx < 4096) { int o = idx / H, c = idx - o * H; g_gc1T[c * H + o] = dup2h(gc1[idx]); return; }
    idx -= 4096;
    if (idx < 4096) { int o = idx / H, c = idx - o * H; g_gc2T[c * H + o] = dup2h(gc2[idx]); return; }
    idx -= 4096;
    if (idx < NNODES) { g_dis[idx] = 1.0f; g_cnt[idx] = 0; }
}

__global__ void k_deg_acc(const int* __restrict__ dst, const float* __restrict__ ew) {
    int e = blockIdx.x * blockDim.x + threadIdx.x;
    if (e < NEDGES) {
        int d = dst[e];
        atomicAdd(&g_dis[d], ew[e]);
        atomicAdd(&g_cnt[d], 1);
    }
}

// rsqrt + single-block exclusive scan (warp-shuffle based)
__global__ void k_scan() {
    __shared__ int wsum[32];
    __shared__ int carry_s;
    int tid = threadIdx.x, lane = tid & 31, wid = tid >> 5;
    for (int i = tid; i < NNODES; i += 1024) g_dis[i] = rsqrtf(g_dis[i]);
    if (tid == 0) carry_s = 0;
    __syncthreads();
    for (int base = 0; base < NNODES; base += 1024) {
        int i = base + tid;
        int v = (i < NNODES) ? g_cnt[i] : 0;
        int s = v;
#pragma unroll
        for (int off = 1; off < 32; off <<= 1) {
            int t = __shfl_up_sync(0xffffffffu, s, off);
            if (lane >= off) s += t;
        }
        if (lane == 31) wsum[wid] = s;
        __syncthreads();
        if (wid == 0) {
            int ws = wsum[lane];
#pragma unroll
            for (int off = 1; off < 32; off <<= 1) {
                int t = __shfl_up_sync(0xffffffffu, ws, off);
                if (lane >= off) ws += t;
            }
            wsum[lane] = ws;
        }
        __syncthreads();
        if (i < NNODES) { g_row[i] = carry_s + (wid ? wsum[wid - 1] : 0) + s - v; g_fill[i] = 0; }
        __syncthreads();
        if (tid == 1023) carry_s += wsum[31];
        __syncthreads();
    }
    if (tid == 0) g_row[NNODES] = carry_s;
}

__global__ void k_fill(const int* __restrict__ src, const int* __restrict__ dst,
                       const float* __restrict__ ew) {
    int e = blockIdx.x * blockDim.x + threadIdx.x;
    if (e >= NEDGES) return;
    int s = src[e], d = dst[e];
    int pos = g_row[d] + atomicAdd(&g_fill[d], 1);
    float nrm = g_dis[s] * ew[e] * g_dis[d];
    g_edge[pos] = ((ull)__float_as_uint(nrm) << 32) | (unsigned)s;
}

// ---------------- pair-window building blocks ----------------
// xs row per (n,c): 10 ull, W[m] = {x[m-1], x[m+5]} for m=0..7 (x[-1]=x[12]=0), 2 pad.
// Output pair P_i = {t=i, t=i+6};  P_i += w_k * W[i+k],  i=0..5, k=0..2.

// stage x (t-order global) into pair-window smem
template <int CI>
__device__ __forceinline__ void stage_global(const float* __restrict__ x, ull* xs,
                                             int tid, int n0) {
    for (int idx = tid; idx < 4 * CI * 12; idx += 128) {
        int nn = idx / (CI * 12);
        int rr = idx - nn * (CI * 12);
        int c = rr / 12;
        int t = rr - c * 12;
        float v = x[(n0 + nn) * (CI * 12) + rr];
        float* row = (float*)(xs + (nn * CI + c) * 10);
        if (t <= 6) row[2 * (t + 1)] = v;      // W[t+1].lo = x[t]
        if (t >= 5) row[2 * (t - 5) + 1] = v;  // W[t-5].hi = x[t]
    }
    for (int idx = tid; idx < 4 * CI; idx += 128) {
        float* row = (float*)(xs + idx * 10);
        row[0] = 0.f;   // W[0].lo = x[-1]
        row[15] = 0.f;  // W[7].hi = x[12]
    }
}

// conv FMA phase reading staged xs; gate+bias applied; pairs returned
template <int CI>
__device__ __forceinline__ void conv_phase(const ull* xs, const float* __restrict__ wT,
                                           const float* __restrict__ b, int g, int o,
                                           float (&rAlo)[6], float (&rAhi)[6],
                                           float (&rBlo)[6], float (&rBhi)[6]) {
    ull PA[6], QA[6], PB[6], QB[6];
#pragma unroll
    for (int i = 0; i < 6; i++) { PA[i] = 0ull; QA[i] = 0ull; PB[i] = 0ull; QB[i] = 0ull; }

    const ulonglong2* epA = reinterpret_cast<const ulonglong2*>(xs + (2 * g) * CI * 10);
    const ulonglong2* epB = reinterpret_cast<const ulonglong2*>(xs + (2 * g + 1) * CI * 10);
    const float4* wv = reinterpret_cast<const float4*>(wT) + o;
    float4 wp4 = wv[0];   // preload c = 0
    float4 wq4 = wv[64];

#pragma unroll 2
    for (int c = 0; c < CI; c++) {
        wv += 128;
        float4 wp4n = wv[0];   // prefetch c+1 (pad row makes last read safe)
        float4 wq4n = wv[64];
        ull w0 = dupr(wp4.x), w1 = dupr(wp4.y), w2 = dupr(wp4.z);
        ull v0 = dupr(wq4.x), v1 = dupr(wq4.y), v2 = dupr(wq4.z);
        {
            ulonglong2 a0 = epA[0], a1 = epA[1], a2 = epA[2], a3 = epA[3];
            epA += 5;
            ull W[8] = {a0.x, a0.y, a1.x, a1.y, a2.x, a2.y, a3.x, a3.y};
#pragma unroll
            for (int i = 0; i < 6; i++) {
                FMA2(PA[i], w0, W[i]);
                FMA2(PA[i], w1, W[i + 1]);
                FMA2(PA[i], w2, W[i + 2]);
                FMA2(QA[i], v0, W[i]);
                FMA2(QA[i], v1, W[i + 1]);
                FMA2(QA[i], v2, W[i + 2]);
            }
        }
        {
            ulonglong2 a0 = epB[0], a1 = epB[1], a2 = epB[2], a3 = epB[3];
            epB += 5;
            ull W[8] = {a0.x, a0.y, a1.x, a1.y, a2.x, a2.y, a3.x, a3.y};
#pragma unroll
            for (int i = 0; i < 6; i++) {
                FMA2(PB[i], w0, W[i]);
                FMA2(PB[i], w1, W[i + 1]);
                FMA2(PB[i], w2, W[i + 2]);
                FMA2(QB[i], v0, W[i]);
                FMA2(QB[i], v1, W[i + 1]);
                FMA2(QB[i], v2, W[i + 2]);
            }
        }
        wp4 = wp4n;
        wq4 = wq4n;
    }

    float bp = b[o], bq = b[64 + o];
#pragma unroll
    for (int i = 0; i < 6; i++) {
        float pl = lof(PA[i]) + bp, ph = hif(PA[i]) + bp;
        float ql = lof(QA[i]) + bq, qh = hif(QA[i]) + bq;
        rAlo[i] = pl * (1.0f / (1.0f + __expf(-ql)));
        rAhi[i] = ph * (1.0f / (1.0f + __expf(-qh)));
        pl = lof(PB[i]) + bp; ph = hif(PB[i]) + bp;
        ql = lof(QB[i]) + bq; qh = hif(QB[i]) + bq;
        rBlo[i] = pl * (1.0f / (1.0f + __expf(-ql)));
        rBhi[i] = ph * (1.0f / (1.0f + __expf(-qh)));
    }
}

// restage held output pairs y (lo6: t=0..5, hi6: t=6..11) into pair-window row for next conv
__device__ __forceinline__ void restage_row(ull* xs, int node_l, int o,
                                            const float (&lo6)[6], const float (&hi6)[6]) {
    ull* q = xs + (node_l * 64 + o) * 10;
    q[0] = packf2(0.0f, lo6[5]);                          // W[0] = {y[-1], y[5]}
#pragma unroll
    for (int m = 1; m < 7; m++) q[m] = packf2(lo6[m - 1], hi6[m - 1]);  // {y[m-1], y[m+5]}
    q[7] = packf2(hi6[0], 0.0f);                          // W[7] = {y[6], y[12]}
}

// write pairs {i, i+6} out in t-order
__device__ __forceinline__ void write12p(float* __restrict__ out, int n, int o,
                                         const float (&lo6)[6], const float (&hi6)[6]) {
    float4* op = reinterpret_cast<float4*>(out + ((size_t)n * 64 + o) * 12);
    op[0] = make_float4(lo6[0], lo6[1], lo6[2], lo6[3]);
    op[1] = make_float4(lo6[4], lo6[5], hi6[0], hi6[1]);
    op[2] = make_float4(hi6[2], hi6[3], hi6[4], hi6[5]);
}

// stage pairs into sb (10-ull row per (node, o))
__device__ __forceinline__ void sb_stage_p(ull* sb, int node_l, int o,
                                           const float (&lo6)[6], const float (&hi6)[6]) {
    ull* q = sb + (node_l * 64 + o) * 10;
#pragma unroll
    for (int i = 0; i < 6; i++) q[i] = packf2(lo6[i], hi6[i]);
}

// mix epilogue: reads sb pairs, FMA2 over 64 channels, writes result pairs
__device__ __forceinline__ void mix_phase(const ull* sm, const ull* __restrict__ gw,
                                          int g, int o,
                                          float (&mAlo)[6], float (&mAhi)[6],
                                          float (&mBlo)[6], float (&mBhi)[6]) {
    ull MA[6], MB[6];
#pragma unroll
    for (int i = 0; i < 6; i++) { MA[i] = 0ull; MB[i] = 0ull; }
    const ulonglong2* spA = reinterpret_cast<const ulonglong2*>(sm + (2 * g) * 64 * 10);
    const ulonglong2* spB = reinterpret_cast<const ulonglong2*>(sm + (2 * g + 1) * 64 * 10);
    const ull* gp = gw + o;
    ull w = gp[0];  // preload c = 0
#pragma unroll 2
    for (int c = 0; c < 64; c++) {
        gp += 64;
        ull wn = gp[0];  // prefetch (pad row covers last iter)
        ulonglong2 a0 = spA[0], a1 = spA[1], a2 = spA[2];
        spA += 5;
        FMA2(MA[0], w, a0.x); FMA2(MA[1], w, a0.y);
        FMA2(MA[2], w, a1.x); FMA2(MA[3], w, a1.y);
        FMA2(MA[4], w, a2.x); FMA2(MA[5], w, a2.y);
        ulonglong2 c0 = spB[0], c1 = spB[1], c2 = spB[2];
        spB += 5;
        FMA2(MB[0], w, c0.x); FMA2(MB[1], w, c0.y);
        FMA2(MB[2], w, c1.x); FMA2(MB[3], w, c1.y);
        FMA2(MB[4], w, c2.x); FMA2(MB[5], w, c2.y);
        w = wn;
    }
#pragma unroll
    for (int i = 0; i < 6; i++) {
        mAlo[i] = lof(MA[i]); mAhi[i] = hif(MA[i]);
        mBlo[i] = lof(MB[i]); mBhi[i] = hif(MB[i]);
    }
}

// ---------------- stage A: tconv1a + mix1 ----------------
template <int CI>
__global__ void __launch_bounds__(128, 5)
k_tconv2_mix(const float* __restrict__ x, const float* __restrict__ wT,
             const float* __restrict__ b, const ull* __restrict__ gw,
             float* __restrict__ out) {
    constexpr int XS = 4 * CI * 10;
    constexpr int SB = 4 * 64 * 10;
    __shared__ __align__(16) ull sm[XS > SB ? XS : SB];
    const int tid = threadIdx.x;
    const int g = tid >> 6;
    const int o = tid & 63;
    const int n0 = blockIdx.x * 4;
    stage_global<CI>(x, sm, tid, n0);
    __syncthreads();
    float rAlo[6], rAhi[6], rBlo[6], rBhi[6];
    conv_phase<CI>(sm, wT, b, g, o, rAlo, rAhi, rBlo, rBhi);

    __syncthreads();  // conv reads of sm done; reuse as sb
    sb_stage_p(sm, 2 * g, o, rAlo, rAhi);
    sb_stage_p(sm, 2 * g + 1, o, rBlo, rBhi);
    __syncthreads();

    float mAlo[6], mAhi[6], mBlo[6], mBhi[6];
    mix_phase(sm, gw, g, o, mAlo, mAhi, mBlo, mBhi);
    write12p(out, n0 + 2 * g, o, mAlo, mAhi);
    write12p(out, n0 + 2 * g + 1, o, mBlo, mBhi);
}

// ---------------- stage B: tconv1b + tconv2a + mix2 (node-local chain) ----------------
__global__ void __launch_bounds__(128, 5)
k_stageB(const float* __restrict__ x, const float* __restrict__ w1,
         const float* __restrict__ b1, const float* __restrict__ w2,
         const float* __restrict__ b2, const ull* __restrict__ gw,
         float* __restrict__ out) {
    constexpr int XS = 4 * H * 10;  // 2560 ull = 20 KB (same for SB)
    __shared__ __align__(16) ull sm[XS];
    const int tid = threadIdx.x;
    const int g = tid >> 6;
    const int o = tid & 63;
    const int n0 = blockIdx.x * 4;
    stage_global<H>(x, sm, tid, n0);
    __syncthreads();
    float rAlo[6], rAhi[6], rBlo[6], rBhi[6];
    conv_phase<H>(sm, w1, b1, g, o, rAlo, rAhi, rBlo, rBhi);   // tconv1b

    __syncthreads();  // conv1 reads done; restage gated output as conv2 input
    restage_row(sm, 2 * g, o, rAlo, rAhi);
    restage_row(sm, 2 * g + 1, o, rBlo, rBhi);
    __syncthreads();
    conv_phase<H>(sm, w2, b2, g, o, rAlo, rAhi, rBlo, rBhi);   // tconv2a

    __syncthreads();  // conv2 reads done; reuse as sb for mix
    sb_stage_p(sm, 2 * g, o, rAlo, rAhi);
    sb_stage_p(sm, 2 * g + 1, o, rBlo, rBhi);
    __syncthreads();

    float mAlo[6], mAhi[6], mBlo[6], mBhi[6];
    mix_phase(sm, gw, g, o, mAlo, mAhi, mBlo, mBhi);
    write12p(out, n0 + 2 * g, o, mAlo, mAhi);
    write12p(out, n0 + 2 * g + 1, o, mBlo, mBhi);
}

// ---------------- stage C: tconv2b + fin ----------------
__global__ void __launch_bounds__(128, 5)
k_tconv2_fin(const float* __restrict__ x, const float* __restrict__ wT,
             const float* __restrict__ b, const float* __restrict__ fw,
             const float* __restrict__ fb, float* __restrict__ out) {
    constexpr int XS = 4 * H * 10;
    __shared__ __align__(16) ull sm[XS];
    const int tid = threadIdx.x;
    const int g = tid >> 6;
    const int o = tid & 63;
    const int n0 = blockIdx.x * 4;
    stage_global<H>(x, sm, tid, n0);
    __syncthreads();
    float rAlo[6], rAhi[6], rBlo[6], rBhi[6];
    conv_phase<H>(sm, wT, b, g, o, rAlo, rAhi, rBlo, rBhi);

    __syncthreads();
    sb_stage_p(sm, 2 * g, o, rAlo, rAhi);
    sb_stage_p(sm, 2 * g + 1, o, rBlo, rBhi);
    __syncthreads();

    // fin: 96 threads: nl(0..3) x oc(0..11) x half(0..1); dot over 32 c x 12 t; shfl add.
    if (tid < 96) {
        int nl = tid / 24;
        int rr = tid - nl * 24;
        int oc = rr >> 1;
        int s2 = rr & 1;
        const ull* gS = sm + (nl * 64 + s2 * 32) * 10;
        const float4* wrow = reinterpret_cast<const float4*>(fw + oc * FEAT + s2 * 32 * 12);
        float acc = 0.0f;
#pragma unroll 4
        for (int c = 0; c < 32; c++) {
            const ulonglong2* sr = reinterpret_cast<const ulonglong2*>(gS + c * 10);
            ulonglong2 a0 = sr[0], a1 = sr[1], a2 = sr[2];
            float4 w0 = wrow[0], w1v = wrow[1], w2 = wrow[2];
            wrow += 3;
            acc += lof(a0.x) * w0.x + lof(a0.y) * w0.y + lof(a1.x) * w0.z + lof(a1.y) * w0.w;
            acc += lof(a2.x) * w1v.x + lof(a2.y) * w1v.y;
            acc += hif(a0.x) * w1v.z + hif(a0.y) * w1v.w;
            acc += hif(a1.x) * w2.x + hif(a1.y) * w2.y + hif(a2.x) * w2.z + hif(a2.y) * w2.w;
        }
        acc += __shfl_xor_sync(0xffffffffu, acc, 1);
        if (s2 == 0) out[(n0 + nl) * 12 + oc] = acc + fb[oc];
    }
}

// ---------------- GCN gather: out[n] = relu(b + dis[n]^2 * x[n] + sum_e nrm*x[src]) --------
__global__ void __launch_bounds__(192)
k_gather(const float* __restrict__ x, float* __restrict__ out, const float* __restrict__ b) {
    const int n = blockIdx.x;
    const int j = threadIdx.x;  // 0..191 float4 slots
    float bb = b[j / 3];
    float ds = g_dis[n];
    float sc = ds * ds;
    const float4* xv = reinterpret_cast<const float4*>(x);
    float4 v = xv[(size_t)n * 192 + j];
    float4 acc = make_float4(bb + sc * v.x, bb + sc * v.y, bb + sc * v.z, bb + sc * v.w);
    int e = g_row[n];
    const int end = g_row[n + 1];
    for (; e + 1 < end; e += 2) {
        ull e0 = __ldg(&g_edge[e]);
        ull e1 = __ldg(&g_edge[e + 1]);
        int s0 = (int)(unsigned)e0, s1 = (int)(unsigned)e1;
        float c0 = __uint_as_float((unsigned)(e0 >> 32));
        float c1 = __uint_as_float((unsigned)(e1 >> 32));
        float4 u0 = xv[(size_t)s0 * 192 + j];
        float4 u1 = xv[(size_t)s1 * 192 + j];
        acc.x += c0 * u0.x + c1 * u1.x;
        acc.y += c0 * u0.y + c1 * u1.y;
        acc.z += c0 * u0.z + c1 * u1.z;
        acc.w += c0 * u0.w + c1 * u1.w;
    }
    if (e < end) {
        ull e0 = __ldg(&g_edge[e]);
        int s0 = (int)(unsigned)e0;
        float c0 = __uint_as_float((unsigned)(e0 >> 32));
        float4 u0 = xv[(size_t)s0 * 192 + j];
        acc.x += c0 * u0.x; acc.y += c0 * u0.y; acc.z += c0 * u0.z; acc.w += c0 * u0.w;
    }
    reinterpret_cast<float4*>(out)[(size_t)n * 192 + j] =
        make_float4(fmaxf(acc.x, 0.f), fmaxf(acc.y, 0.f), fmaxf(acc.z, 0.f), fmaxf(acc.w, 0.f));
}

// ---------------- launch ----------------
extern "C" void kernel_launch(void* const* d_in, const int* in_sizes, int n_in,
                              void* d_out, int out_size) {
    const float* x      = (const float*)d_in[0];
    const int*   ei     = (const int*)d_in[1];
    const int*   src    = ei;
    const int*   dst    = ei + NEDGES;
    const float* ew     = (const float*)d_in[2];
    const float* tc1a_w = (const float*)d_in[3];
    const float* tc1a_b = (const float*)d_in[4];
    const float* gc1_w  = (const float*)d_in[5];
    const float* gc1_b  = (const float*)d_in[6];
    const float* tc1b_w = (const float*)d_in[7];
    const float* tc1b_b = (const float*)d_in[8];
    const float* tc2a_w = (const float*)d_in[9];
    const float* tc2a_b = (const float*)d_in[10];
    const float* gc2_w  = (const float*)d_in[11];
    const float* gc2_b  = (const float*)d_in[12];
    const float* tc2b_w = (const float*)d_in[13];
    const float* tc2b_b = (const float*)d_in[14];
    const float* fin_w  = (const float*)d_in[15];
    const float* fin_b  = (const float*)d_in[16];
    float* out = (float*)d_out;

    float *bA, *bB, *w1a, *w1b, *w2a, *w2b;
    ull *g1, *g2;
    cudaGetSymbolAddress((void**)&bA, g_bufA);
    cudaGetSymbolAddress((void**)&bB, g_bufB);
    cudaGetSymbolAddress((void**)&w1a, g_wt1a);
    cudaGetSymbolAddress((void**)&w1b, g_wt1b);
    cudaGetSymbolAddress((void**)&w2a, g_wt2a);
    cudaGetSymbolAddress((void**)&w2b, g_wt2b);
    cudaGetSymbolAddress((void**)&g1, g_gc1T);
    cudaGetSymbolAddress((void**)&g2, g_gc2T);

    const int NB = NNODES / 4;  // 2500

    // launches 1..3: prep
    const int PREP_TOT = 12288 + 3 * 24576 + 2 * 4096 + NNODES;
    k_prep<<<(PREP_TOT + 255) / 256, 256>>>(tc1a_w, tc1b_w, tc2a_w, tc2b_w, gc1_w, gc2_w);
    k_deg_acc<<<(NEDGES + 255) / 256, 256>>>(dst, ew);
    k_scan<<<1, 1024>>>();

    // launch 4: hot kernel at the ncu capture position
    k_tconv2_mix<CINCH><<<NB, 128>>>(x, w1a, tc1a_b, g1, bA);   // tconv1a + mix1

    // CSR fill, then the rest of the pipeline
    k_fill<<<(NEDGES + 255) / 256, 256>>>(src, dst, ew);
    k_gather<<<NNODES, 192>>>(bA, bB, gc1_b);                    // +bias +selfloop +relu
    k_stageB<<<NB, 128>>>(bB, w1b, tc1b_b, w2a, tc2a_b, g2, bA); // tconv1b + tconv2a + mix2
    k_gather<<<NNODES, 192>>>(bA, bB, gc2_b);
    k_tconv2_fin<<<NB, 128>>>(bB, w2b, tc2b_b, fin_w, fin_b, out);  // tconv2b + fin
}